// round 16
// baseline (speedup 1.0000x reference)
#include <cuda_runtime.h>
#include <cuda_bf16.h>
#include <math.h>
#include <stdint.h>

#define SEQ   1024
#define BAT   4
#define DM    1024
#define NHEAD 16
#define HD    64
#define BNH   (BAT*NHEAD)   // 64
#define SKR   1152
#define SCALE_F 0.125f
#define NEG_BIG -1.0e30f

// ---------------- scratch ----------------
__device__ __nv_bfloat16 g_hb [SEQ*BAT*DM];
__device__ __nv_bfloat16 g_rb [SKR*BAT*DM];
__device__ __nv_bfloat16 g_wt [4*DM*1024];
__device__ __nv_bfloat16 g_wob[DM*1024];
__device__ __nv_bfloat16 g_qb [BNH*SEQ*HD];
__device__ __nv_bfloat16 g_kb [BNH*SEQ*HD];
__device__ __nv_bfloat16 g_vb [BNH*SEQ*HD];
__device__ __nv_bfloat16 g_krb[BNH*SKR*HD];
__device__ __nv_bfloat16 g_avb[BNH*SEQ*HD];
__device__ float g_ck [BNH*SEQ];
__device__ float g_ckr[BNH*SKR];
__device__ float g_ef [BNH*SEQ*2];
__device__ float g_a  [BAT*SEQ];
__device__ float g_ao [SEQ*BAT*DM];

// bf16 mma.sync m16n8k16, fp32 accumulate (in-place)
__device__ __forceinline__ void mma_bf16(float* c, const uint32_t* a, uint32_t b0, uint32_t b1)
{
    asm volatile(
        "mma.sync.aligned.m16n8k16.row.col.f32.bf16.bf16.f32 "
        "{%0,%1,%2,%3}, {%4,%5,%6,%7}, {%8,%9}, {%0,%1,%2,%3};"
        : "+f"(c[0]), "+f"(c[1]), "+f"(c[2]), "+f"(c[3])
        : "r"(a[0]), "r"(a[1]), "r"(a[2]), "r"(a[3]), "r"(b0), "r"(b1));
}

__device__ __forceinline__ void cpa16(void* s, const void* g)
{
    uint32_t sa = (uint32_t)__cvta_generic_to_shared(s);
    asm volatile("cp.async.cg.shared.global [%0], [%1], 16;\n" :: "r"(sa), "l"(g));
}
#define CPA_COMMIT asm volatile("cp.async.commit_group;\n" ::: "memory")
#define CPA_WAIT1  asm volatile("cp.async.wait_group 1;\n" ::: "memory")
#define CPA_WAIT0  asm volatile("cp.async.wait_group 0;\n" ::: "memory")

__device__ __forceinline__ void ldm4t(uint32_t& r0, uint32_t& r1, uint32_t& r2, uint32_t& r3,
                                      const void* p)
{
    uint32_t addr = (uint32_t)__cvta_generic_to_shared(p);
    asm volatile("ldmatrix.sync.aligned.m8n8.x4.trans.shared.b16 {%0,%1,%2,%3}, [%4];\n"
                 : "=r"(r0), "=r"(r1), "=r"(r2), "=r"(r3) : "r"(addr));
}

// ---------------- prep: fp32 -> bf16 conversions ----------------
__global__ void conv_elem(const float* __restrict__ src, __nv_bfloat16* __restrict__ dst, int n)
{
    int i = blockIdx.x * 512 + threadIdx.x;
    if (i < n) dst[i] = __float2bfloat16(src[i]);
}

__global__ void conv_wt(const float* __restrict__ W0, const float* __restrict__ W1,
                        const float* __restrict__ W2, const float* __restrict__ W3)
{
    __shared__ float t[32][33];
    const float* W = (blockIdx.z == 0) ? W0 : (blockIdx.z == 1) ? W1 :
                     (blockIdx.z == 2) ? W2 : W3;
    __nv_bfloat16* Wt = g_wt + (size_t)blockIdx.z * DM * 1024;
    int k0 = blockIdx.x * 32, n0 = blockIdx.y * 32;
    int tx = threadIdx.x & 31, ty = threadIdx.x >> 5;
#pragma unroll
    for (int r = 0; r < 32; r += 8)
        t[ty + r][tx] = W[(size_t)(k0 + ty + r) * 1024 + n0 + tx];
    __syncthreads();
#pragma unroll
    for (int r = 0; r < 32; r += 8)
        Wt[(size_t)(n0 + ty + r) * 1024 + k0 + tx] = __float2bfloat16(t[tx][ty + r]);
}

// ---------------- projection GEMM (bf16, cp.async double-buffered) --------------
#define PB_STAGE 9216
#define PB_BYTES (4 * PB_STAGE * 2)

__global__ __launch_bounds__(256, 2) void proj_bf(const __nv_bfloat16* __restrict__ in,
                                                  int nrows, int mode)
{
    extern __shared__ __nv_bfloat16 pbs[];
    const __nv_bfloat16* Wt;
    __nv_bfloat16* outb;
    int c0;
    if (mode == 0) {
        int sel = blockIdx.y >> 3;
        Wt   = g_wt + (size_t)sel * DM * 1024;
        outb = (sel == 0) ? g_qb : (sel == 1) ? g_kb : g_vb;
        c0   = (blockIdx.y & 7) * 128;
    } else {
        Wt = g_wt + (size_t)3 * DM * 1024; outb = g_krb; c0 = blockIdx.y * 128;
    }
    int b    = blockIdx.z;
    int row0 = blockIdx.x * 128;

    int tid  = threadIdx.x;
    int lane = tid & 31, wid = tid >> 5;
    int wm = wid >> 1, wn = wid & 1;
    int g  = lane >> 2, tg = lane & 3;

    float acc[2][8][4];
#pragma unroll
    for (int mt = 0; mt < 2; mt++)
#pragma unroll
        for (int nt = 0; nt < 8; nt++)
#pragma unroll
            for (int e = 0; e < 4; e++) acc[mt][nt][e] = 0.f;

    auto load_stage = [&](int s, int k0) {
        __nv_bfloat16* As = pbs + s * PB_STAGE;
        __nv_bfloat16* Bs = pbs + 2 * PB_STAGE + s * PB_STAGE;
#pragma unroll
        for (int q = 0; q < 4; q++) {
            int idx = q * 256 + tid;
            int rr = idx >> 3, c16 = (idx & 7) * 8;
            cpa16(&As[rr * 72 + c16], in + ((size_t)(row0 + rr) * BAT + b) * DM + k0 + c16);
        }
#pragma unroll
        for (int q = 0; q < 4; q++) {
            int idx = q * 256 + tid;
            int nn = idx >> 3, c16 = (idx & 7) * 8;
            cpa16(&Bs[nn * 72 + c16], Wt + (size_t)(c0 + nn) * 1024 + k0 + c16);
        }
        CPA_COMMIT;
    };

    load_stage(0, 0);
    int buf = 0;
    for (int k0 = 0; k0 < DM; k0 += 64) {
        bool has_next = (k0 + 64 < DM);
        if (has_next) load_stage(buf ^ 1, k0 + 64);
        if (has_next) { CPA_WAIT1; } else { CPA_WAIT0; }
        __syncthreads();

        const __nv_bfloat16* As = pbs + buf * PB_STAGE;
        const __nv_bfloat16* Bs = pbs + 2 * PB_STAGE + buf * PB_STAGE;
#pragma unroll
        for (int k8 = 0; k8 < 4; k8++) {
            int kk2 = k8 * 16 + 2 * tg;
            uint32_t a[2][4];
#pragma unroll
            for (int mt = 0; mt < 2; mt++) {
                int r0 = wm * 32 + mt * 16 + g;
                a[mt][0] = *(const uint32_t*)&As[r0 * 72 + kk2];
                a[mt][1] = *(const uint32_t*)&As[(r0 + 8) * 72 + kk2];
                a[mt][2] = *(const uint32_t*)&As[r0 * 72 + kk2 + 8];
                a[mt][3] = *(const uint32_t*)&As[(r0 + 8) * 72 + kk2 + 8];
            }
#pragma unroll
            for (int nt = 0; nt < 8; nt++) {
                int nn = wn * 64 + nt * 8 + g;
                uint32_t b0 = *(const uint32_t*)&Bs[nn * 72 + kk2];
                uint32_t b1 = *(const uint32_t*)&Bs[nn * 72 + kk2 + 8];
#pragma unroll
                for (int mt = 0; mt < 2; mt++) mma_bf16(acc[mt][nt], a[mt], b0, b1);
            }
        }
        __syncthreads();
        buf ^= 1;
    }

    int head = (c0 + wn * 64) >> 6;
    size_t rowbase = (size_t)(b * NHEAD + head) * nrows + row0 + wm * 32;
#pragma unroll
    for (int mt = 0; mt < 2; mt++) {
#pragma unroll
        for (int nt = 0; nt < 8; nt++) {
            int d = nt * 8 + 2 * tg;
            size_t rlo = rowbase + mt * 16 + g;
            *(__nv_bfloat162*)(outb + rlo * HD + d) =
                __float22bfloat162_rn(make_float2(acc[mt][nt][0], acc[mt][nt][1]));
            *(__nv_bfloat162*)(outb + (rlo + 8) * HD + d) =
                __float22bfloat162_rn(make_float2(acc[mt][nt][2], acc[mt][nt][3]));
        }
    }
}

// ---------------- segment labels -----------------
__global__ void seg_kernel(const float* __restrict__ seg)
{
    int b = blockIdx.x;
    int i = threadIdx.x;
    g_a[b * SEQ + i] = seg[((size_t)i * BAT + b) * 2 + 1];
}

// ---------------- ck / ckr dot products --------------------------
__global__ __launch_bounds__(256) void ckdots_kernel(const float* __restrict__ rwb,
                                                     const float* __restrict__ rrb)
{
    int bn = blockIdx.y;
    int n  = bn & (NHEAD - 1);
    int wid  = threadIdx.x >> 5;
    int lane = threadIdx.x & 31;
    int j = blockIdx.x * 8 + wid;
    if (j >= SKR) return;
    {
        const __nv_bfloat16* kr = g_krb + ((size_t)bn * SKR + j) * HD;
        float s = rrb[n * HD + lane] * __bfloat162float(kr[lane])
                + rrb[n * HD + 32 + lane] * __bfloat162float(kr[32 + lane]);
#pragma unroll
        for (int o = 16; o; o >>= 1) s += __shfl_down_sync(0xffffffffu, s, o);
        if (lane == 0) g_ckr[bn * SKR + j] = s;
    }
    if (j < SEQ) {
        const __nv_bfloat16* kp = g_kb + ((size_t)bn * SEQ + j) * HD;
        float s = rwb[n * HD + lane] * __bfloat162float(kp[lane])
                + rwb[n * HD + 32 + lane] * __bfloat162float(kp[32 + lane]);
#pragma unroll
        for (int o = 16; o; o >>= 1) s += __shfl_down_sync(0xffffffffu, s, o);
        if (lane == 0) g_ck[bn * SEQ + j] = s;
    }
}

// ---------------- ef kernel ------
__global__ __launch_bounds__(256) void ef_kernel(const float* __restrict__ rsb,
                                                 const float* __restrict__ se)
{
    int bn = blockIdx.y;
    int n  = bn & (NHEAD - 1);
    int wid  = threadIdx.x >> 5;
    int lane = threadIdx.x & 31;
    int i = blockIdx.x * 8 + wid;
    const __nv_bfloat16* qp = g_qb + ((size_t)bn * SEQ + i) * HD;
    float q0 = __bfloat162float(qp[lane]) + rsb[n * HD + lane];
    float q1 = __bfloat162float(qp[32 + lane]) + rsb[n * HD + 32 + lane];
    float e0 = q0 * se[(0 * NHEAD + n) * HD + lane] + q1 * se[(0 * NHEAD + n) * HD + 32 + lane];
    float e1 = q0 * se[(1 * NHEAD + n) * HD + lane] + q1 * se[(1 * NHEAD + n) * HD + 32 + lane];
#pragma unroll
    for (int o = 16; o; o >>= 1) {
        e0 += __shfl_down_sync(0xffffffffu, e0, o);
        e1 += __shfl_down_sync(0xffffffffu, e1, o);
    }
    if (lane == 0) {
        g_ef[((size_t)bn * SEQ + i) * 2 + 0] = e0;
        g_ef[((size_t)bn * SEQ + i) * 2 + 1] = e1;
    }
}

// ============== fused attention: cp.async pipelined, Q in registers ==============
// smem: buf0 @0 (18432B), buf1 @18432, BDb[128][260]bf16 @36864, f32 pool @103424
#define AB0      0
#define AB1      18432
#define ATB_BD   36864
#define ATB_F32  103424
#define AT_BYTES (ATB_F32 + 1792*4)   // 110592

__global__ __launch_bounds__(512, 2) void attn_fused()
{
    extern __shared__ char smc[];
    __nv_bfloat16* bufs[2] = { (__nv_bfloat16*)(smc + AB0), (__nv_bfloat16*)(smc + AB1) };
    __nv_bfloat16* BDb = (__nv_bfloat16*)(smc + ATB_BD);
    float* f32  = (float*)(smc + ATB_F32);
    float* smM  = f32;
    float* smL  = f32 + 128;
    float* sRsc = f32 + 256;
    float* wred = f32 + 384;
    float* sck  = f32 + 896;
    float* sckr = f32 + 1024;
    float* sef  = f32 + 1280;
    float* sai  = f32 + 1536;
    float* saj  = f32 + 1664;

    int bn = blockIdx.z;
    int b  = bn >> 4;
    int it = (int)(gridDim.x - 1 - blockIdx.x);
    int i0 = it * 128;

    int tid  = threadIdx.x;
    int lane = tid & 31, wid = tid >> 5;
    int wm = wid >> 2, wn = wid & 3;
    int g  = lane >> 2, tg = lane & 3;
    int r0base = wm * 32 + g;

    if (tid < 128) {
        sai[tid] = g_a[b * SEQ + i0 + tid];
        smM[tid] = -3.0e38f;
        smL[tid] = 0.f;
    } else if (tid < 256) {
        int x = tid - 128;
        sef[x]       = g_ef[((size_t)bn * SEQ + i0) * 2 + x];
        sef[x + 128] = g_ef[((size_t)bn * SEQ + i0) * 2 + x + 128];
    }
    // load Q into buf0, extract fragments to registers
#pragma unroll
    for (int q = 0; q < 2; q++) {
        int idx = q * 512 + tid;
        int rr = idx >> 3, h8 = (idx & 7) * 8;
        *(float4*)&bufs[0][rr * 72 + h8] =
            *(const float4*)(g_qb + ((size_t)bn * SEQ + i0 + rr) * HD + h8);
    }
    __syncthreads();
    uint32_t aq[4][2][4];
#pragma unroll
    for (int k8 = 0; k8 < 4; k8++) {
        int kk2 = k8 * 16 + 2 * tg;
#pragma unroll
        for (int mt = 0; mt < 2; mt++) {
            int r0 = r0base + mt * 16;
            aq[k8][mt][0] = *(const uint32_t*)&bufs[0][r0 * 72 + kk2];
            aq[k8][mt][1] = *(const uint32_t*)&bufs[0][(r0 + 8) * 72 + kk2];
            aq[k8][mt][2] = *(const uint32_t*)&bufs[0][r0 * 72 + kk2 + 8];
            aq[k8][mt][3] = *(const uint32_t*)&bufs[0][(r0 + 8) * 72 + kk2 + 8];
        }
    }
    __syncthreads();

    // tile copy: 128 rows x 64 bf16, dst stride 72
    auto tile_cp = [&](__nv_bfloat16* dst, const __nv_bfloat16* src) {
#pragma unroll
        for (int q = 0; q < 2; q++) {
            int idx = q * 512 + tid;
            int rr = idx >> 3, c16 = (idx & 7) * 8;
            cpa16(&dst[rr * 72 + c16], src + (size_t)rr * HD + c16);
        }
        CPA_COMMIT;
    };

    float acc_o[2][2][4];
#pragma unroll
    for (int mt = 0; mt < 2; mt++)
#pragma unroll
        for (int nt = 0; nt < 2; nt++)
#pragma unroll
            for (int e = 0; e < 4; e++) acc_o[mt][nt][e] = 0.f;

    int cur = 0;
    // issue first load: L_first(0) = KR(h=0) of tile 0
    tile_cp(bufs[0], g_krb + ((size_t)bn * SKR + (SEQ - i0 - 127)) * HD);

    for (int jt = 0; jt <= it; jt++) {
        int j0 = jt * 128;
        int pmin = SEQ + j0 - i0 - 127;
        int loR = jt & 1;
        int hiR = loR ^ 1;
        int hfirst = (jt == 0) ? 0 : 1;
        int hlast  = (jt == 0) ? ((it == 0) ? 0 : 1) : ((jt < it) ? 1 : 0);

        // ---- BD halves ----
        for (int h = hfirst; h <= hlast; h++) {
            __syncthreads();                       // prior compute done with buf[cur^1]
            if (h == hfirst) {
                if (tid < 128) {
                    sck[tid] = g_ck[(size_t)bn * SEQ + j0 + tid];
                    saj[tid] = g_a[b * SEQ + j0 + tid];
                }
                if (tid < 255) sckr[tid] = g_ckr[(size_t)bn * SKR + pmin + tid];
            }
            if (h < hlast) tile_cp(bufs[cur ^ 1], g_krb + ((size_t)bn * SKR + pmin + (h + 1) * 128) * HD);
            else           tile_cp(bufs[cur ^ 1], g_kb + ((size_t)bn * SEQ + j0) * HD);
            CPA_WAIT1;
            __syncthreads();                       // buf[cur] (KR h) ready

            const __nv_bfloat16* KB = bufs[cur];
            int reg = (h == 0) ? loR : hiR;
            float sc[2][4][4];
#pragma unroll
            for (int mt = 0; mt < 2; mt++)
#pragma unroll
                for (int nt = 0; nt < 4; nt++)
#pragma unroll
                    for (int e = 0; e < 4; e++) sc[mt][nt][e] = 0.f;
#pragma unroll
            for (int k8 = 0; k8 < 4; k8++) {
                int kk2 = k8 * 16 + 2 * tg;
#pragma unroll
                for (int nt = 0; nt < 4; nt++) {
                    int nn = wn * 32 + nt * 8 + g;
                    uint32_t b0 = *(const uint32_t*)&KB[nn * 72 + kk2];
                    uint32_t b1 = *(const uint32_t*)&KB[nn * 72 + kk2 + 8];
#pragma unroll
                    for (int mt = 0; mt < 2; mt++) mma_bf16(sc[mt][nt], aq[k8][mt], b0, b1);
                }
            }
#pragma unroll
            for (int mt = 0; mt < 2; mt++) {
#pragma unroll
                for (int nt = 0; nt < 4; nt++) {
                    int r = r0base + mt * 16;
                    int c = reg * 128 + wn * 32 + nt * 8 + 2 * tg;
                    *(__nv_bfloat162*)&BDb[r * 260 + c] =
                        __float22bfloat162_rn(make_float2(sc[mt][nt][0], sc[mt][nt][1]));
                    *(__nv_bfloat162*)&BDb[(r + 8) * 260 + c] =
                        __float22bfloat162_rn(make_float2(sc[mt][nt][2], sc[mt][nt][3]));
                }
            }
            cur ^= 1;
        }

        // ---- AC ----
        __syncthreads();                           // BD readers done with buf[cur^1]; BDb stores ordered
        if (hfirst > hlast) {                      // diagonal tile (no BD): biases here
            if (tid < 128) {
                sck[tid] = g_ck[(size_t)bn * SEQ + j0 + tid];
                saj[tid] = g_a[b * SEQ + j0 + tid];
            }
            if (tid < 255) sckr[tid] = g_ckr[(size_t)bn * SKR + pmin + tid];
        }
        tile_cp(bufs[cur ^ 1], g_vb + ((size_t)bn * SEQ + j0) * HD);   // V row-major
        CPA_WAIT1;
        __syncthreads();                           // buf[cur] (K) ready; biases visible

        {
            const __nv_bfloat16* KB = bufs[cur];
            float sc[2][4][4];
#pragma unroll
            for (int mt = 0; mt < 2; mt++)
#pragma unroll
                for (int nt = 0; nt < 4; nt++)
#pragma unroll
                    for (int e = 0; e < 4; e++) sc[mt][nt][e] = 0.f;
#pragma unroll
            for (int k8 = 0; k8 < 4; k8++) {
                int kk2 = k8 * 16 + 2 * tg;
#pragma unroll
                for (int nt = 0; nt < 4; nt++) {
                    int nn = wn * 32 + nt * 8 + g;
                    uint32_t b0 = *(const uint32_t*)&KB[nn * 72 + kk2];
                    uint32_t b1 = *(const uint32_t*)&KB[nn * 72 + kk2 + 8];
#pragma unroll
                    for (int mt = 0; mt < 2; mt++) mma_bf16(sc[mt][nt], aq[k8][mt], b0, b1);
                }
            }
            cur ^= 1;                              // cur now = V slot

            // ---- combine ----
            float pmax[2][2];
#pragma unroll
            for (int mt = 0; mt < 2; mt++)
#pragma unroll
                for (int half = 0; half < 2; half++) pmax[mt][half] = -3.0e38f;

#pragma unroll
            for (int mt = 0; mt < 2; mt++) {
#pragma unroll
                for (int half = 0; half < 2; half++) {
                    int rr = r0base + mt * 16 + half * 8;
                    float ai  = sai[rr];
                    float ef0 = sef[rr * 2 + 0];
                    float ef1 = sef[rr * 2 + 1];
#pragma unroll
                    for (int nt = 0; nt < 4; nt++) {
                        int cc = wn * 32 + nt * 8 + 2 * tg;
#pragma unroll
                        for (int e = 0; e < 2; e++) {
                            int jj = cc + e;
                            float s;
                            if (jt == it && jj > rr) {
                                s = NEG_BIG;
                            } else {
                                int d = jj - rr + 127;
                                int col = (d < 128) ? (loR * 128 + d) : (hiR * 128 + d - 128);
                                float bdv = __bfloat162float(BDb[rr * 260 + col]);
                                float efv = (ai != saj[jj]) ? ef1 : ef0;
                                s = (sc[mt][nt][half * 2 + e] + bdv + sckr[d]
                                     + sck[jj] + efv) * SCALE_F;
                            }
                            sc[mt][nt][half * 2 + e] = s;
                            pmax[mt][half] = fmaxf(pmax[mt][half], s);
                        }
                    }
                }
            }
#pragma unroll
            for (int mt = 0; mt < 2; mt++)
#pragma unroll
                for (int half = 0; half < 2; half++) {
                    float v = pmax[mt][half];
                    v = fmaxf(v, __shfl_xor_sync(0xffffffffu, v, 1));
                    v = fmaxf(v, __shfl_xor_sync(0xffffffffu, v, 2));
                    pmax[mt][half] = v;
                }
            if (tg == 0) {
#pragma unroll
                for (int mt = 0; mt < 2; mt++)
#pragma unroll
                    for (int half = 0; half < 2; half++)
                        wred[wn * 128 + r0base + mt * 16 + half * 8] = pmax[mt][half];
            }
            __syncthreads();
            if (tid < 128) {
                float newm = fmaxf(fmaxf(wred[tid], wred[128 + tid]),
                                   fmaxf(wred[256 + tid], wred[384 + tid]));
                newm = fmaxf(smM[tid], newm);
                float rs = __expf(smM[tid] - newm);
                sRsc[tid] = rs;
                smM[tid]  = newm;
                smL[tid] *= rs;
            }
            __syncthreads();

            float psum[2][2] = {{0.f, 0.f}, {0.f, 0.f}};
#pragma unroll
            for (int mt = 0; mt < 2; mt++) {
#pragma unroll
                for (int half = 0; half < 2; half++) {
                    int rr = r0base + mt * 16 + half * 8;
                    float mrow = smM[rr];
#pragma unroll
                    for (int nt = 0; nt < 4; nt++) {
                        int cc = wn * 32 + nt * 8 + 2 * tg;
                        float p0 = __expf(sc[mt][nt][half * 2 + 0] - mrow);
                        float p1 = __expf(sc[mt][nt][half * 2 + 1] - mrow);
                        psum[mt][half] += p0 + p1;
                        *(__nv_bfloat162*)&BDb[rr * 260 + loR * 128 + cc] =
                            __float22bfloat162_rn(make_float2(p0, p1));
                    }
                }
            }
#pragma unroll
            for (int mt = 0; mt < 2; mt++)
#pragma unroll
                for (int half = 0; half < 2; half++) {
                    float v = psum[mt][half];
                    v += __shfl_xor_sync(0xffffffffu, v, 1);
                    v += __shfl_xor_sync(0xffffffffu, v, 2);
                    psum[mt][half] = v;
                }
            if (tg == 0) {
#pragma unroll
                for (int mt = 0; mt < 2; mt++)
#pragma unroll
                    for (int half = 0; half < 2; half++)
                        wred[wn * 128 + r0base + mt * 16 + half * 8] = psum[mt][half];
            }
#pragma unroll
            for (int mt = 0; mt < 2; mt++) {
                float rs0 = sRsc[r0base + mt * 16];
                float rs1 = sRsc[r0base + mt * 16 + 8];
#pragma unroll
                for (int nt = 0; nt < 2; nt++) {
                    acc_o[mt][nt][0] *= rs0;
                    acc_o[mt][nt][1] *= rs0;
                    acc_o[mt][nt][2] *= rs1;
                    acc_o[mt][nt][3] *= rs1;
                }
            }
        }
        __syncthreads();                           // K slot free (AC done everywhere); wred visible
        if (jt < it) {
            // L_first(jt+1): KR(h=1) if jt+1<it else K(jt+1)
            int j0n = (jt + 1) * 128;
            int pminn = SEQ + j0n - i0 - 127;
            if (jt + 1 < it) tile_cp(bufs[cur ^ 1], g_krb + ((size_t)bn * SKR + pminn + 128) * HD);
            else             tile_cp(bufs[cur ^ 1], g_kb + ((size_t)bn * SEQ + j0n) * HD);
            CPA_WAIT1;
        } else {
            CPA_WAIT0;
        }
        __syncthreads();                           // V ready
        if (tid < 128)
            smL[tid] += wred[tid] + wred[128 + tid] + wred[256 + tid] + wred[384 + tid];

        // ---- PV: P (BDb lo) @ V (ldmatrix.trans from buf[cur]) ----
        {
            const __nv_bfloat16* Vb = bufs[cur];
            int sel = lane >> 3;
            int vrow_off = (lane & 7) + ((sel & 1) << 3);
            int vcol = wn * 16 + ((sel & 2) ? 8 : 0);
#pragma unroll
            for (int k8 = 0; k8 < 8; k8++) {
                int kk2 = k8 * 16 + 2 * tg;
                uint32_t a[2][4];
#pragma unroll
                for (int mt = 0; mt < 2; mt++) {
                    int r0 = r0base + mt * 16;
                    a[mt][0] = *(const uint32_t*)&BDb[r0 * 260 + loR * 128 + kk2];
                    a[mt][1] = *(const uint32_t*)&BDb[(r0 + 8) * 260 + loR * 128 + kk2];
                    a[mt][2] = *(const uint32_t*)&BDb[r0 * 260 + loR * 128 + kk2 + 8];
                    a[mt][3] = *(const uint32_t*)&BDb[(r0 + 8) * 260 + loR * 128 + kk2 + 8];
                }
                uint32_t v0, v1, v2, v3;
                ldm4t(v0, v1, v2, v3, &Vb[(k8 * 16 + vrow_off) * 72 + vcol]);
#pragma unroll
                for (int mt = 0; mt < 2; mt++) {
                    mma_bf16(acc_o[mt][0], a[mt], v0, v1);
                    mma_bf16(acc_o[mt][1], a[mt], v2, v3);
                }
            }
            cur ^= 1;
        }
    }
    __syncthreads();

    // ---- finalize ----
#pragma unroll
    for (int mt = 0; mt < 2; mt++) {
#pragma unroll
        for (int half = 0; half < 2; half++) {
            int rr = r0base + mt * 16 + half * 8;
            float invl = 1.f / smL[rr];
#pragma unroll
            for (int nt = 0; nt < 2; nt++) {
                int c = wn * 16 + nt * 8 + 2 * tg;
                *(__nv_bfloat162*)(g_avb + ((size_t)bn * SEQ + i0 + rr) * HD + c) =
                    __float22bfloat162_rn(make_float2(acc_o[mt][nt][half * 2 + 0] * invl,
                                                      acc_o[mt][nt][half * 2 + 1] * invl));
            }
        }
    }
}

// ---------------- Wo GEMM + residual (bf16) ----------------
__global__ __launch_bounds__(256, 2) void out_bf(const float* __restrict__ hin)
{
    extern __shared__ __nv_bfloat16 obs[];
    int row0 = blockIdx.x * 128;
    int c0   = blockIdx.y * 128;

    int tid  = threadIdx.x;
    int lane = tid & 31, wid = tid >> 5;
    int wm = wid >> 1, wn = wid & 1;
    int g  = lane >> 2, tg = lane & 3;

    float acc[2][8][4];
#pragma unroll
    for (int mt = 0; mt < 2; mt++)
#pragma unroll
        for (int nt = 0; nt < 8; nt++)
#pragma unroll
            for (int e = 0; e < 4; e++) acc[mt][nt][e] = 0.f;

    auto load_stage = [&](int s, int k0) {
        __nv_bfloat16* As = obs + s * PB_STAGE;
        __nv_bfloat16* Bs = obs + 2 * PB_STAGE + s * PB_STAGE;
        int n = k0 >> 6;
#pragma unroll
        for (int q = 0; q < 4; q++) {
            int idx = q * 256 + tid;
            int rr = idx >> 3, d8 = (idx & 7) * 8;
            int row = row0 + rr;
            int bb = row & 3, ii = row >> 2;
            cpa16(&As[rr * 72 + d8], g_avb + ((size_t)(bb * NHEAD + n) * SEQ + ii) * HD + d8);
        }
#pragma unroll
        for (int q = 0; q < 4; q++) {
            int idx = q * 256 + tid;
            int nn = idx >> 3, c16 = (idx & 7) * 8;
            cpa16(&Bs[nn * 72 + c16], g_wob + (size_t)(c0 + nn) * 1024 + k0 + c16);
        }
        CPA_COMMIT;
    };

    load_stage(0, 0);
    int buf = 0;
    for (int k0 = 0; k0 < DM; k0 += 64) {
        bool has_next = (k0 + 64 < DM);
        if (has_next) load_stage(buf ^ 1, k0 + 64);
        if (has_next) { CPA_WAIT1; } else { CPA_WAIT0; }
        __syncthreads();

        const __nv_bfloat16* As = obs + buf * PB_STAGE;
        const __nv_bfloat16* Bs = obs + 2 * PB_STAGE + buf * PB_STAGE;
#pragma unroll
        for (int k8 = 0; k8 < 4; k8++) {
            int kk2 = k8 * 16 + 2 * tg;
            uint32_t a[2][4];
#pragma unroll
            for (int mt = 0; mt < 2; mt++) {
                int r0 = wm * 32 + mt * 16 + g;
                a[mt][0] = *(const uint32_t*)&As[r0 * 72 + kk2];
                a[mt][1] = *(const uint32_t*)&As[(r0 + 8) * 72 + kk2];
                a[mt][2] = *(const uint32_t*)&As[r0 * 72 + kk2 + 8];
                a[mt][3] = *(const uint32_t*)&As[(r0 + 8) * 72 + kk2 + 8];
            }
#pragma unroll
            for (int nt = 0; nt < 8; nt++) {
                int nn = wn * 64 + nt * 8 + g;
                uint32_t b0 = *(const uint32_t*)&Bs[nn * 72 + kk2];
                uint32_t b1 = *(const uint32_t*)&Bs[nn * 72 + kk2 + 8];
#pragma unroll
                for (int mt = 0; mt < 2; mt++) mma_bf16(acc[mt][nt], a[mt], b0, b1);
            }
        }
        __syncthreads();
        buf ^= 1;
    }
#pragma unroll
    for (int mt = 0; mt < 2; mt++) {
#pragma unroll
        for (int nt = 0; nt < 8; nt++) {
            int col = c0 + wn * 64 + nt * 8 + 2 * tg;
#pragma unroll
            for (int half = 0; half < 2; half++) {
                int row = row0 + wm * 32 + mt * 16 + g + half * 8;
                const float2 hres = *(const float2*)(hin + (size_t)row * DM + col);
                float2 s = make_float2(acc[mt][nt][half * 2 + 0] + hres.x,
                                       acc[mt][nt][half * 2 + 1] + hres.y);
                *(float2*)(g_ao + (size_t)row * DM + col) = s;
            }
        }
    }
}

// ---------------- LayerNorm --------------------------------------------
__global__ __launch_bounds__(256) void ln_kernel(const float* __restrict__ lns,
                                                 const float* __restrict__ lnb,
                                                 float* __restrict__ out)
{
    int row = blockIdx.x;
    int tid = threadIdx.x;
    const float* x = g_ao + (size_t)row * DM;
    float v[4];
    float s = 0.f;
#pragma unroll
    for (int k = 0; k < 4; k++) { v[k] = x[tid + k * 256]; s += v[k]; }
    __shared__ float red[256];
    red[tid] = s; __syncthreads();
    for (int t = 128; t > 0; t >>= 1) { if (tid < t) red[tid] += red[tid + t]; __syncthreads(); }
    float mu = red[0] * (1.f / DM);
    __syncthreads();
    float s2 = 0.f;
#pragma unroll
    for (int k = 0; k < 4; k++) { float d = v[k] - mu; s2 += d * d; }
    red[tid] = s2; __syncthreads();
    for (int t = 128; t > 0; t >>= 1) { if (tid < t) red[tid] += red[tid + t]; __syncthreads(); }
    float var = red[0] * (1.f / DM);
    float inv = rsqrtf(var + 1e-12f);
#pragma unroll
    for (int k = 0; k < 4; k++) {
        int j = tid + k * 256;
        out[(size_t)row * DM + j] = (v[k] - mu) * inv * lns[j] + lnb[j];
    }
}

// ---------------- launch --------------------------------------------------------
extern "C" void kernel_launch(void* const* d_in, const int* in_sizes, int n_in,
                              void* d_out, int out_size)
{
    const float* h   = (const float*)d_in[0];
    const float* r   = (const float*)d_in[1];
    const float* seg = (const float*)d_in[2];
    const float* Wq  = (const float*)d_in[4];
    const float* Wk  = (const float*)d_in[5];
    const float* Wv  = (const float*)d_in[6];
    const float* Wo  = (const float*)d_in[7];
    const float* Wr  = (const float*)d_in[8];
    const float* rwb = (const float*)d_in[9];
    const float* rrb = (const float*)d_in[10];
    const float* rsb = (const float*)d_in[11];
    const float* se  = (const float*)d_in[12];
    const float* lns = (const float*)d_in[13];
    const float* lnb = (const float*)d_in[14];
    float* out = (float*)d_out;

    cudaFuncSetAttribute(attn_fused, cudaFuncAttributeMaxDynamicSharedMemorySize, AT_BYTES);
    cudaFuncSetAttribute(proj_bf, cudaFuncAttributeMaxDynamicSharedMemorySize, PB_BYTES);
    cudaFuncSetAttribute(out_bf,  cudaFuncAttributeMaxDynamicSharedMemorySize, PB_BYTES);

    __nv_bfloat16 *hb_p, *rb_p, *wob_p;
    cudaGetSymbolAddress((void**)&hb_p, g_hb);
    cudaGetSymbolAddress((void**)&rb_p, g_rb);
    cudaGetSymbolAddress((void**)&wob_p, g_wob);
    conv_elem<<<(SEQ*BAT*DM + 511)/512, 512>>>(h, hb_p, SEQ*BAT*DM);
    conv_elem<<<(SKR*BAT*DM + 511)/512, 512>>>(r, rb_p, SKR*BAT*DM);
    conv_elem<<<(DM*1024 + 511)/512, 512>>>(Wo, wob_p, DM*1024);
    conv_wt<<<dim3(32, 32, 4), 256>>>(Wq, Wk, Wv, Wr);

    proj_bf<<<dim3(SEQ/128, 24, BAT), 256, PB_BYTES>>>(hb_p, SEQ, 0);
    proj_bf<<<dim3(SKR/128,  8, BAT), 256, PB_BYTES>>>(rb_p, SKR, 1);

    seg_kernel<<<BAT, SEQ>>>(seg);
    ckdots_kernel<<<dim3((SKR + 7) / 8, BNH), 256>>>(rwb, rrb);
    ef_kernel<<<dim3(SEQ / 8, BNH), 256>>>(rsb, se);

    attn_fused<<<dim3(SEQ/128, 1, BNH), 512, AT_BYTES>>>();

    out_bf<<<dim3((SEQ*BAT)/128, DM/128), 256, PB_BYTES>>>(h);
    ln_kernel<<<SEQ*BAT, 256>>>(lns, lnb, out);
}

// round 17
// speedup vs baseline: 1.2069x; 1.2069x over previous
#include <cuda_runtime.h>
#include <cuda_bf16.h>
#include <math.h>
#include <stdint.h>

#define SEQ   1024
#define BAT   4
#define DM    1024
#define NHEAD 16
#define HD    64
#define BNH   (BAT*NHEAD)   // 64
#define SKR   1152
#define SCALE_F 0.125f
#define NEG_BIG -1.0e30f

// ---------------- scratch ----------------
__device__ __nv_bfloat16 g_hb [SEQ*BAT*DM];
__device__ __nv_bfloat16 g_rb [SKR*BAT*DM];
__device__ __nv_bfloat16 g_wt [4*DM*1024];
__device__ __nv_bfloat16 g_wob[DM*1024];
__device__ __nv_bfloat16 g_qb [BNH*SEQ*HD];
__device__ __nv_bfloat16 g_kb [BNH*SEQ*HD];
__device__ __nv_bfloat16 g_vb [BNH*SEQ*HD];
__device__ __nv_bfloat16 g_krb[BNH*SKR*HD];
__device__ __nv_bfloat16 g_avb[BNH*SEQ*HD];
__device__ float g_ck [BNH*SEQ];
__device__ float g_ckr[BNH*SKR];
__device__ float g_ef [BNH*SEQ*2];
__device__ float g_a  [BAT*SEQ];
__device__ float g_ao [SEQ*BAT*DM];

// bf16 mma.sync m16n8k16, fp32 accumulate (in-place)
__device__ __forceinline__ void mma_bf16(float* c, const uint32_t* a, uint32_t b0, uint32_t b1)
{
    asm volatile(
        "mma.sync.aligned.m16n8k16.row.col.f32.bf16.bf16.f32 "
        "{%0,%1,%2,%3}, {%4,%5,%6,%7}, {%8,%9}, {%0,%1,%2,%3};"
        : "+f"(c[0]), "+f"(c[1]), "+f"(c[2]), "+f"(c[3])
        : "r"(a[0]), "r"(a[1]), "r"(a[2]), "r"(a[3]), "r"(b0), "r"(b1));
}

__device__ __forceinline__ void cpa16(void* s, const void* g)
{
    uint32_t sa = (uint32_t)__cvta_generic_to_shared(s);
    asm volatile("cp.async.cg.shared.global [%0], [%1], 16;\n" :: "r"(sa), "l"(g));
}
#define CPA_COMMIT asm volatile("cp.async.commit_group;\n" ::: "memory")
#define CPA_WAIT1  asm volatile("cp.async.wait_group 1;\n" ::: "memory")
#define CPA_WAIT0  asm volatile("cp.async.wait_group 0;\n" ::: "memory")

// ---------------- prep: fp32 -> bf16 conversions (single launch) ----------------
#define N_H  (SEQ*BAT*DM)
#define N_R  (SKR*BAT*DM)
#define N_WO (DM*1024)
__global__ void conv_all(const float* __restrict__ h, const float* __restrict__ r,
                         const float* __restrict__ Wo)
{
    int i = blockIdx.x * 512 + threadIdx.x;
    if (i < N_H) {
        g_hb[i] = __float2bfloat16(h[i]);
    } else if (i < N_H + N_R) {
        int j = i - N_H;
        g_rb[j] = __float2bfloat16(r[j]);
    } else if (i < N_H + N_R + N_WO) {
        int j = i - N_H - N_R;
        g_wob[j] = __float2bfloat16(Wo[j]);
    }
}

__global__ void conv_wt(const float* __restrict__ W0, const float* __restrict__ W1,
                        const float* __restrict__ W2, const float* __restrict__ W3)
{
    __shared__ float t[32][33];
    const float* W = (blockIdx.z == 0) ? W0 : (blockIdx.z == 1) ? W1 :
                     (blockIdx.z == 2) ? W2 : W3;
    __nv_bfloat16* Wt = g_wt + (size_t)blockIdx.z * DM * 1024;
    int k0 = blockIdx.x * 32, n0 = blockIdx.y * 32;
    int tx = threadIdx.x & 31, ty = threadIdx.x >> 5;
#pragma unroll
    for (int r = 0; r < 32; r += 8)
        t[ty + r][tx] = W[(size_t)(k0 + ty + r) * 1024 + n0 + tx];
    __syncthreads();
#pragma unroll
    for (int r = 0; r < 32; r += 8)
        Wt[(size_t)(n0 + ty + r) * 1024 + k0 + tx] = __float2bfloat16(t[tx][ty + r]);
}

// ---------------- projection GEMM (bf16, cp.async double-buffered, merged) -------
#define PB_STAGE 9216
#define PB_BYTES (4 * PB_STAGE * 2)

__global__ __launch_bounds__(256, 2) void proj_bf(const __nv_bfloat16* __restrict__ inh,
                                                  const __nv_bfloat16* __restrict__ inr)
{
    extern __shared__ __nv_bfloat16 pbs[];
    const __nv_bfloat16* in;
    const __nv_bfloat16* Wt;
    __nv_bfloat16* outb;
    int c0, nrows;
    if (blockIdx.y < 24) {
        if (blockIdx.x >= 8) return;      // QKV: 8 row-tiles only
        int sel = blockIdx.y / 8;
        in   = inh; nrows = SEQ;
        Wt   = g_wt + (size_t)sel * DM * 1024;
        outb = (sel == 0) ? g_qb : (sel == 1) ? g_kb : g_vb;
        c0   = (blockIdx.y % 8) * 128;
    } else {
        in   = inr; nrows = SKR;
        Wt   = g_wt + (size_t)3 * DM * 1024;
        outb = g_krb;
        c0   = (blockIdx.y - 24) * 128;
    }
    int b    = blockIdx.z;
    int row0 = blockIdx.x * 128;

    int tid  = threadIdx.x;
    int lane = tid & 31, wid = tid >> 5;
    int wm = wid >> 1, wn = wid & 1;
    int g  = lane >> 2, tg = lane & 3;

    float acc[2][8][4];
#pragma unroll
    for (int mt = 0; mt < 2; mt++)
#pragma unroll
        for (int nt = 0; nt < 8; nt++)
#pragma unroll
            for (int e = 0; e < 4; e++) acc[mt][nt][e] = 0.f;

    auto load_stage = [&](int s, int k0) {
        __nv_bfloat16* As = pbs + s * PB_STAGE;
        __nv_bfloat16* Bs = pbs + 2 * PB_STAGE + s * PB_STAGE;
#pragma unroll
        for (int q = 0; q < 4; q++) {
            int idx = q * 256 + tid;
            int rr = idx >> 3, c16 = (idx & 7) * 8;
            cpa16(&As[rr * 72 + c16], in + ((size_t)(row0 + rr) * BAT + b) * DM + k0 + c16);
        }
#pragma unroll
        for (int q = 0; q < 4; q++) {
            int idx = q * 256 + tid;
            int nn = idx >> 3, c16 = (idx & 7) * 8;
            cpa16(&Bs[nn * 72 + c16], Wt + (size_t)(c0 + nn) * 1024 + k0 + c16);
        }
        CPA_COMMIT;
    };

    load_stage(0, 0);
    int buf = 0;
    for (int k0 = 0; k0 < DM; k0 += 64) {
        bool has_next = (k0 + 64 < DM);
        if (has_next) load_stage(buf ^ 1, k0 + 64);
        if (has_next) { CPA_WAIT1; } else { CPA_WAIT0; }
        __syncthreads();

        const __nv_bfloat16* As = pbs + buf * PB_STAGE;
        const __nv_bfloat16* Bs = pbs + 2 * PB_STAGE + buf * PB_STAGE;
#pragma unroll
        for (int k8 = 0; k8 < 4; k8++) {
            int kk2 = k8 * 16 + 2 * tg;
            uint32_t a[2][4];
#pragma unroll
            for (int mt = 0; mt < 2; mt++) {
                int r0 = wm * 32 + mt * 16 + g;
                a[mt][0] = *(const uint32_t*)&As[r0 * 72 + kk2];
                a[mt][1] = *(const uint32_t*)&As[(r0 + 8) * 72 + kk2];
                a[mt][2] = *(const uint32_t*)&As[r0 * 72 + kk2 + 8];
                a[mt][3] = *(const uint32_t*)&As[(r0 + 8) * 72 + kk2 + 8];
            }
#pragma unroll
            for (int nt = 0; nt < 8; nt++) {
                int nn = wn * 64 + nt * 8 + g;
                uint32_t b0 = *(const uint32_t*)&Bs[nn * 72 + kk2];
                uint32_t b1 = *(const uint32_t*)&Bs[nn * 72 + kk2 + 8];
#pragma unroll
                for (int mt = 0; mt < 2; mt++) mma_bf16(acc[mt][nt], a[mt], b0, b1);
            }
        }
        __syncthreads();
        buf ^= 1;
    }

    int head = (c0 + wn * 64) >> 6;
    size_t rowbase = (size_t)(b * NHEAD + head) * nrows + row0 + wm * 32;
#pragma unroll
    for (int mt = 0; mt < 2; mt++) {
#pragma unroll
        for (int nt = 0; nt < 8; nt++) {
            int d = nt * 8 + 2 * tg;
            size_t rlo = rowbase + mt * 16 + g;
            *(__nv_bfloat162*)(outb + rlo * HD + d) =
                __float22bfloat162_rn(make_float2(acc[mt][nt][0], acc[mt][nt][1]));
            *(__nv_bfloat162*)(outb + (rlo + 8) * HD + d) =
                __float22bfloat162_rn(make_float2(acc[mt][nt][2], acc[mt][nt][3]));
        }
    }
}

// ---------------- segment labels -----------------
__global__ void seg_kernel(const float* __restrict__ seg)
{
    int b = blockIdx.x;
    int i = threadIdx.x;
    g_a[b * SEQ + i] = seg[((size_t)i * BAT + b) * 2 + 1];
}

// ---------------- ck / ckr dot products --------------------------
__global__ __launch_bounds__(256) void ckdots_kernel(const float* __restrict__ rwb,
                                                     const float* __restrict__ rrb)
{
    int bn = blockIdx.y;
    int n  = bn & (NHEAD - 1);
    int wid  = threadIdx.x >> 5;
    int lane = threadIdx.x & 31;
    int j = blockIdx.x * 8 + wid;
    if (j >= SKR) return;
    {
        const __nv_bfloat16* kr = g_krb + ((size_t)bn * SKR + j) * HD;
        float s = rrb[n * HD + lane] * __bfloat162float(kr[lane])
                + rrb[n * HD + 32 + lane] * __bfloat162float(kr[32 + lane]);
#pragma unroll
        for (int o = 16; o; o >>= 1) s += __shfl_down_sync(0xffffffffu, s, o);
        if (lane == 0) g_ckr[bn * SKR + j] = s;
    }
    if (j < SEQ) {
        const __nv_bfloat16* kp = g_kb + ((size_t)bn * SEQ + j) * HD;
        float s = rwb[n * HD + lane] * __bfloat162float(kp[lane])
                + rwb[n * HD + 32 + lane] * __bfloat162float(kp[32 + lane]);
#pragma unroll
        for (int o = 16; o; o >>= 1) s += __shfl_down_sync(0xffffffffu, s, o);
        if (lane == 0) g_ck[bn * SEQ + j] = s;
    }
}

// ---------------- ef kernel ------
__global__ __launch_bounds__(256) void ef_kernel(const float* __restrict__ rsb,
                                                 const float* __restrict__ se)
{
    int bn = blockIdx.y;
    int n  = bn & (NHEAD - 1);
    int wid  = threadIdx.x >> 5;
    int lane = threadIdx.x & 31;
    int i = blockIdx.x * 8 + wid;
    const __nv_bfloat16* qp = g_qb + ((size_t)bn * SEQ + i) * HD;
    float q0 = __bfloat162float(qp[lane]) + rsb[n * HD + lane];
    float q1 = __bfloat162float(qp[32 + lane]) + rsb[n * HD + 32 + lane];
    float e0 = q0 * se[(0 * NHEAD + n) * HD + lane] + q1 * se[(0 * NHEAD + n) * HD + 32 + lane];
    float e1 = q0 * se[(1 * NHEAD + n) * HD + lane] + q1 * se[(1 * NHEAD + n) * HD + 32 + lane];
#pragma unroll
    for (int o = 16; o; o >>= 1) {
        e0 += __shfl_down_sync(0xffffffffu, e0, o);
        e1 += __shfl_down_sync(0xffffffffu, e1, o);
    }
    if (lane == 0) {
        g_ef[((size_t)bn * SEQ + i) * 2 + 0] = e0;
        g_ef[((size_t)bn * SEQ + i) * 2 + 1] = e1;
    }
}

// ============== fused attention (bf16 operands, fp32 accum) — R15 version ========
#define ATB_QH   0
#define ATB_KB   18432
#define ATB_BD   36864
#define ATB_F32  103424
#define AT_BYTES (ATB_F32 + 1792*4)   // 110592

__global__ __launch_bounds__(512, 2) void attn_fused()
{
    extern __shared__ char smc[];
    __nv_bfloat16* Qh  = (__nv_bfloat16*)(smc + ATB_QH);
    __nv_bfloat16* KBh = (__nv_bfloat16*)(smc + ATB_KB);
    __nv_bfloat16* VT  = (__nv_bfloat16*)(smc + ATB_KB);
    __nv_bfloat16* BDb = (__nv_bfloat16*)(smc + ATB_BD);
    float* f32  = (float*)(smc + ATB_F32);
    float* smM  = f32;
    float* smL  = f32 + 128;
    float* sRsc = f32 + 256;
    float* wred = f32 + 384;
    float* sck  = f32 + 896;
    float* sckr = f32 + 1024;
    float* sef  = f32 + 1280;
    float* sai  = f32 + 1536;
    float* saj  = f32 + 1664;

    int bn = blockIdx.z;
    int b  = bn >> 4;
    int it = (int)(gridDim.x - 1 - blockIdx.x);
    int i0 = it * 128;

    int tid  = threadIdx.x;
    int lane = tid & 31, wid = tid >> 5;
    int wm = wid >> 2, wn = wid & 3;
    int g  = lane >> 2, tg = lane & 3;

    if (tid < 128) {
        sai[tid] = g_a[b * SEQ + i0 + tid];
        smM[tid] = -3.0e38f;
        smL[tid] = 0.f;
    } else if (tid < 256) {
        int x = tid - 128;
        sef[x]       = g_ef[((size_t)bn * SEQ + i0) * 2 + x];
        sef[x + 128] = g_ef[((size_t)bn * SEQ + i0) * 2 + x + 128];
    }
#pragma unroll
    for (int q = 0; q < 2; q++) {
        int idx = q * 512 + tid;
        int rr = idx >> 3, h8 = (idx & 7) * 8;
        *(float4*)&Qh[rr * 72 + h8] =
            *(const float4*)(g_qb + ((size_t)bn * SEQ + i0 + rr) * HD + h8);
    }

    float acc_o[2][2][4];
#pragma unroll
    for (int mt = 0; mt < 2; mt++)
#pragma unroll
        for (int nt = 0; nt < 2; nt++)
#pragma unroll
            for (int e = 0; e < 4; e++) acc_o[mt][nt][e] = 0.f;

    int r0base = wm * 32 + g;

    for (int jt = 0; jt <= it; jt++) {
        int j0 = jt * 128;
        int pmin = SEQ + j0 - i0 - 127;
        int loR = jt & 1;
        int hiR = loR ^ 1;

        if (tid < 128) {
            sck[tid] = g_ck[(size_t)bn * SEQ + j0 + tid];
            saj[tid] = g_a[b * SEQ + j0 + tid];
        }
        if (tid < 255) sckr[tid] = g_ckr[(size_t)bn * SKR + pmin + tid];

        int hfirst = (jt == 0) ? 0 : 1;
        int hlast  = (jt == 0) ? ((it == 0) ? 0 : 1) : ((jt < it) ? 1 : 0);
        for (int h = hfirst; h <= hlast; h++) {
            int reg = (h == 0) ? loR : hiR;
#pragma unroll
            for (int q = 0; q < 2; q++) {
                int idx = q * 512 + tid;
                int rr = idx >> 3, h8 = (idx & 7) * 8;
                *(float4*)&KBh[rr * 72 + h8] =
                    *(const float4*)(g_krb + ((size_t)bn * SKR + pmin + h * 128 + rr) * HD + h8);
            }
            __syncthreads();

            float bd[2][4][4];
#pragma unroll
            for (int mt = 0; mt < 2; mt++)
#pragma unroll
                for (int nt = 0; nt < 4; nt++)
#pragma unroll
                    for (int e = 0; e < 4; e++) bd[mt][nt][e] = 0.f;
#pragma unroll
            for (int k8 = 0; k8 < 4; k8++) {
                int kk2 = k8 * 16 + 2 * tg;
                uint32_t a[2][4];
#pragma unroll
                for (int mt = 0; mt < 2; mt++) {
                    int r0 = r0base + mt * 16;
                    a[mt][0] = *(const uint32_t*)&Qh[r0 * 72 + kk2];
                    a[mt][1] = *(const uint32_t*)&Qh[(r0 + 8) * 72 + kk2];
                    a[mt][2] = *(const uint32_t*)&Qh[r0 * 72 + kk2 + 8];
                    a[mt][3] = *(const uint32_t*)&Qh[(r0 + 8) * 72 + kk2 + 8];
                }
#pragma unroll
                for (int nt = 0; nt < 4; nt++) {
                    int nn = wn * 32 + nt * 8 + g;
                    uint32_t b0 = *(const uint32_t*)&KBh[nn * 72 + kk2];
                    uint32_t b1 = *(const uint32_t*)&KBh[nn * 72 + kk2 + 8];
#pragma unroll
                    for (int mt = 0; mt < 2; mt++) mma_bf16(bd[mt][nt], a[mt], b0, b1);
                }
            }
#pragma unroll
            for (int mt = 0; mt < 2; mt++) {
#pragma unroll
                for (int nt = 0; nt < 4; nt++) {
                    int r = r0base + mt * 16;
                    int c = reg * 128 + wn * 32 + nt * 8 + 2 * tg;
                    *(__nv_bfloat162*)&BDb[r * 260 + c] =
                        __float22bfloat162_rn(make_float2(bd[mt][nt][0], bd[mt][nt][1]));
                    *(__nv_bfloat162*)&BDb[(r + 8) * 260 + c] =
                        __float22bfloat162_rn(make_float2(bd[mt][nt][2], bd[mt][nt][3]));
                }
            }
            __syncthreads();
        }

        // ---- AC ----
#pragma unroll
        for (int q = 0; q < 2; q++) {
            int idx = q * 512 + tid;
            int rr = idx >> 3, h8 = (idx & 7) * 8;
            *(float4*)&KBh[rr * 72 + h8] =
                *(const float4*)(g_kb + ((size_t)bn * SEQ + j0 + rr) * HD + h8);
        }
        __syncthreads();

        float acc[2][4][4];
#pragma unroll
        for (int mt = 0; mt < 2; mt++)
#pragma unroll
            for (int nt = 0; nt < 4; nt++)
#pragma unroll
                for (int e = 0; e < 4; e++) acc[mt][nt][e] = 0.f;
#pragma unroll
        for (int k8 = 0; k8 < 4; k8++) {
            int kk2 = k8 * 16 + 2 * tg;
            uint32_t a[2][4];
#pragma unroll
            for (int mt = 0; mt < 2; mt++) {
                int r0 = r0base + mt * 16;
                a[mt][0] = *(const uint32_t*)&Qh[r0 * 72 + kk2];
                a[mt][1] = *(const uint32_t*)&Qh[(r0 + 8) * 72 + kk2];
                a[mt][2] = *(const uint32_t*)&Qh[r0 * 72 + kk2 + 8];
                a[mt][3] = *(const uint32_t*)&Qh[(r0 + 8) * 72 + kk2 + 8];
            }
#pragma unroll
            for (int nt = 0; nt < 4; nt++) {
                int nn = wn * 32 + nt * 8 + g;
                uint32_t b0 = *(const uint32_t*)&KBh[nn * 72 + kk2];
                uint32_t b1 = *(const uint32_t*)&KBh[nn * 72 + kk2 + 8];
#pragma unroll
                for (int mt = 0; mt < 2; mt++) mma_bf16(acc[mt][nt], a[mt], b0, b1);
            }
        }

        // ---- combine ----
        float pmax[2][2];
#pragma unroll
        for (int mt = 0; mt < 2; mt++)
#pragma unroll
            for (int half = 0; half < 2; half++) pmax[mt][half] = -3.0e38f;

#pragma unroll
        for (int mt = 0; mt < 2; mt++) {
#pragma unroll
            for (int half = 0; half < 2; half++) {
                int rr = r0base + mt * 16 + half * 8;
                float ai  = sai[rr];
                float ef0 = sef[rr * 2 + 0];
                float ef1 = sef[rr * 2 + 1];
#pragma unroll
                for (int nt = 0; nt < 4; nt++) {
                    int cc = wn * 32 + nt * 8 + 2 * tg;
#pragma unroll
                    for (int e = 0; e < 2; e++) {
                        int jj = cc + e;
                        float s;
                        if (jt == it && jj > rr) {
                            s = NEG_BIG;
                        } else {
                            int d = jj - rr + 127;
                            int col = (d < 128) ? (loR * 128 + d) : (hiR * 128 + d - 128);
                            float bdv = __bfloat162float(BDb[rr * 260 + col]);
                            float efv = (ai != saj[jj]) ? ef1 : ef0;
                            s = (acc[mt][nt][half * 2 + e] + bdv + sckr[d]
                                 + sck[jj] + efv) * SCALE_F;
                        }
                        acc[mt][nt][half * 2 + e] = s;
                        pmax[mt][half] = fmaxf(pmax[mt][half], s);
                    }
                }
            }
        }
#pragma unroll
        for (int mt = 0; mt < 2; mt++)
#pragma unroll
            for (int half = 0; half < 2; half++) {
                float v = pmax[mt][half];
                v = fmaxf(v, __shfl_xor_sync(0xffffffffu, v, 1));
                v = fmaxf(v, __shfl_xor_sync(0xffffffffu, v, 2));
                pmax[mt][half] = v;
            }
        if (tg == 0) {
#pragma unroll
            for (int mt = 0; mt < 2; mt++)
#pragma unroll
                for (int half = 0; half < 2; half++)
                    wred[wn * 128 + r0base + mt * 16 + half * 8] = pmax[mt][half];
        }
        __syncthreads();
        if (tid < 128) {
            float newm = fmaxf(fmaxf(wred[tid], wred[128 + tid]),
                               fmaxf(wred[256 + tid], wred[384 + tid]));
            newm = fmaxf(smM[tid], newm);
            float rs = __expf(smM[tid] - newm);
            sRsc[tid] = rs;
            smM[tid]  = newm;
            smL[tid] *= rs;
        }
        __syncthreads();

        float psum[2][2] = {{0.f, 0.f}, {0.f, 0.f}};
#pragma unroll
        for (int mt = 0; mt < 2; mt++) {
#pragma unroll
            for (int half = 0; half < 2; half++) {
                int rr = r0base + mt * 16 + half * 8;
                float mrow = smM[rr];
#pragma unroll
                for (int nt = 0; nt < 4; nt++) {
                    int cc = wn * 32 + nt * 8 + 2 * tg;
                    float p0 = __expf(acc[mt][nt][half * 2 + 0] - mrow);
                    float p1 = __expf(acc[mt][nt][half * 2 + 1] - mrow);
                    psum[mt][half] += p0 + p1;
                    *(__nv_bfloat162*)&BDb[rr * 260 + loR * 128 + cc] =
                        __float22bfloat162_rn(make_float2(p0, p1));
                }
            }
        }
#pragma unroll
        for (int mt = 0; mt < 2; mt++)
#pragma unroll
            for (int half = 0; half < 2; half++) {
                float v = psum[mt][half];
                v += __shfl_xor_sync(0xffffffffu, v, 1);
                v += __shfl_xor_sync(0xffffffffu, v, 2);
                psum[mt][half] = v;
            }
        if (tg == 0) {
#pragma unroll
            for (int mt = 0; mt < 2; mt++)
#pragma unroll
                for (int half = 0; half < 2; half++)
                    wred[wn * 128 + r0base + mt * 16 + half * 8] = psum[mt][half];
        }
#pragma unroll
        for (int mt = 0; mt < 2; mt++) {
            float rs0 = sRsc[r0base + mt * 16];
            float rs1 = sRsc[r0base + mt * 16 + 8];
#pragma unroll
            for (int nt = 0; nt < 2; nt++) {
                acc_o[mt][nt][0] *= rs0;
                acc_o[mt][nt][1] *= rs0;
                acc_o[mt][nt][2] *= rs1;
                acc_o[mt][nt][3] *= rs1;
            }
        }
#pragma unroll
        for (int q = 0; q < 2; q++) {
            int idx = q * 512 + tid;
            int jj = idx >> 3, d8 = (idx & 7) * 8;
            float4 v4 = *(const float4*)(g_vb + ((size_t)bn * SEQ + j0 + jj) * HD + d8);
            const __nv_bfloat16* hv = (const __nv_bfloat16*)&v4;
#pragma unroll
            for (int e = 0; e < 8; e++)
                VT[(d8 + e) * 136 + jj] = hv[e];
        }
        __syncthreads();
        if (tid < 128)
            smL[tid] += wred[tid] + wred[128 + tid] + wred[256 + tid] + wred[384 + tid];

#pragma unroll
        for (int k8 = 0; k8 < 8; k8++) {
            int kk2 = k8 * 16 + 2 * tg;
            uint32_t a[2][4];
#pragma unroll
            for (int mt = 0; mt < 2; mt++) {
                int r0 = r0base + mt * 16;
                a[mt][0] = *(const uint32_t*)&BDb[r0 * 260 + loR * 128 + kk2];
                a[mt][1] = *(const uint32_t*)&BDb[(r0 + 8) * 260 + loR * 128 + kk2];
                a[mt][2] = *(const uint32_t*)&BDb[r0 * 260 + loR * 128 + kk2 + 8];
                a[mt][3] = *(const uint32_t*)&BDb[(r0 + 8) * 260 + loR * 128 + kk2 + 8];
            }
#pragma unroll
            for (int nt = 0; nt < 2; nt++) {
                int nn = wn * 16 + nt * 8 + g;
                uint32_t b0 = *(const uint32_t*)&VT[nn * 136 + kk2];
                uint32_t b1 = *(const uint32_t*)&VT[nn * 136 + kk2 + 8];
#pragma unroll
                for (int mt = 0; mt < 2; mt++) mma_bf16(acc_o[mt][nt], a[mt], b0, b1);
            }
        }
        __syncthreads();
    }

    // ---- finalize: av bf16 ----
#pragma unroll
    for (int mt = 0; mt < 2; mt++) {
#pragma unroll
        for (int half = 0; half < 2; half++) {
            int rr = r0base + mt * 16 + half * 8;
            float invl = 1.f / smL[rr];
#pragma unroll
            for (int nt = 0; nt < 2; nt++) {
                int c = wn * 16 + nt * 8 + 2 * tg;
                *(__nv_bfloat162*)(g_avb + ((size_t)bn * SEQ + i0 + rr) * HD + c) =
                    __float22bfloat162_rn(make_float2(acc_o[mt][nt][half * 2 + 0] * invl,
                                                      acc_o[mt][nt][half * 2 + 1] * invl));
            }
        }
    }
}

// ---------------- Wo GEMM + residual (bf16) ----------------
__global__ __launch_bounds__(256, 2) void out_bf(const float* __restrict__ hin)
{
    extern __shared__ __nv_bfloat16 obs[];
    int row0 = blockIdx.x * 128;
    int c0   = blockIdx.y * 128;

    int tid  = threadIdx.x;
    int lane = tid & 31, wid = tid >> 5;
    int wm = wid >> 1, wn = wid & 1;
    int g  = lane >> 2, tg = lane & 3;

    float acc[2][8][4];
#pragma unroll
    for (int mt = 0; mt < 2; mt++)
#pragma unroll
        for (int nt = 0; nt < 8; nt++)
#pragma unroll
            for (int e = 0; e < 4; e++) acc[mt][nt][e] = 0.f;

    auto load_stage = [&](int s, int k0) {
        __nv_bfloat16* As = obs + s * PB_STAGE;
        __nv_bfloat16* Bs = obs + 2 * PB_STAGE + s * PB_STAGE;
        int n = k0 >> 6;
#pragma unroll
        for (int q = 0; q < 4; q++) {
            int idx = q * 256 + tid;
            int rr = idx >> 3, d8 = (idx & 7) * 8;
            int row = row0 + rr;
            int bb = row & 3, ii = row >> 2;
            cpa16(&As[rr * 72 + d8], g_avb + ((size_t)(bb * NHEAD + n) * SEQ + ii) * HD + d8);
        }
#pragma unroll
        for (int q = 0; q < 4; q++) {
            int idx = q * 256 + tid;
            int nn = idx >> 3, c16 = (idx & 7) * 8;
            cpa16(&Bs[nn * 72 + c16], g_wob + (size_t)(c0 + nn) * 1024 + k0 + c16);
        }
        CPA_COMMIT;
    };

    load_stage(0, 0);
    int buf = 0;
    for (int k0 = 0; k0 < DM; k0 += 64) {
        bool has_next = (k0 + 64 < DM);
        if (has_next) load_stage(buf ^ 1, k0 + 64);
        if (has_next) { CPA_WAIT1; } else { CPA_WAIT0; }
        __syncthreads();

        const __nv_bfloat16* As = obs + buf * PB_STAGE;
        const __nv_bfloat16* Bs = obs + 2 * PB_STAGE + buf * PB_STAGE;
#pragma unroll
        for (int k8 = 0; k8 < 4; k8++) {
            int kk2 = k8 * 16 + 2 * tg;
            uint32_t a[2][4];
#pragma unroll
            for (int mt = 0; mt < 2; mt++) {
                int r0 = wm * 32 + mt * 16 + g;
                a[mt][0] = *(const uint32_t*)&As[r0 * 72 + kk2];
                a[mt][1] = *(const uint32_t*)&As[(r0 + 8) * 72 + kk2];
                a[mt][2] = *(const uint32_t*)&As[r0 * 72 + kk2 + 8];
                a[mt][3] = *(const uint32_t*)&As[(r0 + 8) * 72 + kk2 + 8];
            }
#pragma unroll
            for (int nt = 0; nt < 8; nt++) {
                int nn = wn * 64 + nt * 8 + g;
                uint32_t b0 = *(const uint32_t*)&Bs[nn * 72 + kk2];
                uint32_t b1 = *(const uint32_t*)&Bs[nn * 72 + kk2 + 8];
#pragma unroll
                for (int mt = 0; mt < 2; mt++) mma_bf16(acc[mt][nt], a[mt], b0, b1);
            }
        }
        __syncthreads();
        buf ^= 1;
    }
#pragma unroll
    for (int mt = 0; mt < 2; mt++) {
#pragma unroll
        for (int nt = 0; nt < 8; nt++) {
            int col = c0 + wn * 64 + nt * 8 + 2 * tg;
#pragma unroll
            for (int half = 0; half < 2; half++) {
                int row = row0 + wm * 32 + mt * 16 + g + half * 8;
                const float2 hres = *(const float2*)(hin + (size_t)row * DM + col);
                float2 s = make_float2(acc[mt][nt][half * 2 + 0] + hres.x,
                                       acc[mt][nt][half * 2 + 1] + hres.y);
                *(float2*)(g_ao + (size_t)row * DM + col) = s;
            }
        }
    }
}

// ---------------- LayerNorm --------------------------------------------
__global__ __launch_bounds__(256) void ln_kernel(const float* __restrict__ lns,
                                                 const float* __restrict__ lnb,
                                                 float* __restrict__ out)
{
    int row = blockIdx.x;
    int tid = threadIdx.x;
    const float* x = g_ao + (size_t)row * DM;
    float v[4];
    float s = 0.f;
#pragma unroll
    for (int k = 0; k < 4; k++) { v[k] = x[tid + k * 256]; s += v[k]; }
    __shared__ float red[256];
    red[tid] = s; __syncthreads();
    for (int t = 128; t > 0; t >>= 1) { if (tid < t) red[tid] += red[tid + t]; __syncthreads(); }
    float mu = red[0] * (1.f / DM);
    __syncthreads();
    float s2 = 0.f;
#pragma unroll
    for (int k = 0; k < 4; k++) { float d = v[k] - mu; s2 += d * d; }
    red[tid] = s2; __syncthreads();
    for (int t = 128; t > 0; t >>= 1) { if (tid < t) red[tid] += red[tid + t]; __syncthreads(); }
    float var = red[0] * (1.f / DM);
    float inv = rsqrtf(var + 1e-12f);
#pragma unroll
    for (int k = 0; k < 4; k++) {
        int j = tid + k * 256;
        out[(size_t)row * DM + j] = (v[k] - mu) * inv * lns[j] + lnb[j];
    }
}

// ---------------- launch --------------------------------------------------------
extern "C" void kernel_launch(void* const* d_in, const int* in_sizes, int n_in,
                              void* d_out, int out_size)
{
    const float* h   = (const float*)d_in[0];
    const float* r   = (const float*)d_in[1];
    const float* seg = (const float*)d_in[2];
    const float* Wq  = (const float*)d_in[4];
    const float* Wk  = (const float*)d_in[5];
    const float* Wv  = (const float*)d_in[6];
    const float* Wo  = (const float*)d_in[7];
    const float* Wr  = (const float*)d_in[8];
    const float* rwb = (const float*)d_in[9];
    const float* rrb = (const float*)d_in[10];
    const float* rsb = (const float*)d_in[11];
    const float* se  = (const float*)d_in[12];
    const float* lns = (const float*)d_in[13];
    const float* lnb = (const float*)d_in[14];
    float* out = (float*)d_out;

    cudaFuncSetAttribute(attn_fused, cudaFuncAttributeMaxDynamicSharedMemorySize, AT_BYTES);
    cudaFuncSetAttribute(proj_bf, cudaFuncAttributeMaxDynamicSharedMemorySize, PB_BYTES);
    cudaFuncSetAttribute(out_bf,  cudaFuncAttributeMaxDynamicSharedMemorySize, PB_BYTES);

    __nv_bfloat16 *hb_p, *rb_p;
    cudaGetSymbolAddress((void**)&hb_p, g_hb);
    cudaGetSymbolAddress((void**)&rb_p, g_rb);

    conv_all<<<(N_H + N_R + N_WO + 511) / 512, 512>>>(h, r, Wo);
    conv_wt<<<dim3(32, 32, 4), 256>>>(Wq, Wk, Wv, Wr);

    proj_bf<<<dim3(SKR/128, 32, BAT), 256, PB_BYTES>>>(hb_p, rb_p);

    seg_kernel<<<BAT, SEQ>>>(seg);
    ckdots_kernel<<<dim3((SKR + 7) / 8, BNH), 256>>>(rwb, rrb);
    ef_kernel<<<dim3(SEQ / 8, BNH), 256>>>(rsb, se);

    attn_fused<<<dim3(SEQ/128, 1, BNH), 512, AT_BYTES>>>();

    out_bf<<<dim3((SEQ*BAT)/128, DM/128), 256, PB_BYTES>>>(h);
    ln_kernel<<<SEQ*BAT, 256>>>(lns, lnb, out);
}